// round 1
// baseline (speedup 1.0000x reference)
#include <cuda_runtime.h>

// ---------------------------------------------------------------------------
// WaveConv3d: 2-level db4 3D DWT (periodic pad 8) -> per-voxel channel mix on
// the 8 coarsest bands -> inverse DWT (level-1 details are zero, so lo-only).
//
// Shapes: x (8,40,64,64,64); w_k (40,40,23,23,23); out (8,40,64,64,64).
// DWT sizes: 64 -> 37 -> 23 (K = (n+8)/2 + 1 with pad=8, stride 2, L=8).
// ---------------------------------------------------------------------------

#define NV 12167            // 23^3
#define BC 320              // B*C = 8*40

__constant__ float c_lo[8] = {
  -0.010597401784997278f,  0.032883011666982945f,  0.030841381835986965f,
  -0.18703481171888114f,  -0.02798376941698385f,   0.6308807679295904f,
   0.7148465705525415f,    0.23037781330885523f };
// hi[k] = (-1)^k * lo[7-k]
__constant__ float c_hi[8] = {
   0.23037781330885523f,  -0.7148465705525415f,    0.6308807679295904f,
   0.02798376941698385f,  -0.18703481171888114f,  -0.030841381835986965f,
   0.032883011666982945f,  0.010597401784997278f };

// Ping-pong scratch (max live tensor = 8*40*37*64*64 = 48,496,640 floats)
__device__ float g_buf1[48496640];
__device__ float g_buf2[48496640];

// ---------------------------------------------------------------------------
// Forward DWT along a middle axis. Tensor viewed as (outer, n, inner),
// output (outer, K, inner).  lo[j] = sum_s c_lo[s] * x[(2j-1-s) mod n].
// ---------------------------------------------------------------------------
template<bool HI>
__global__ void dwt_k(const float* __restrict__ in,
                      float* __restrict__ olo, float* __restrict__ ohi,
                      int n, int K, int inner, long long total) {
    long long idx = (long long)blockIdx.x * blockDim.x + threadIdx.x;
    if (idx >= total) return;
    int ii       = (int)(idx % inner);
    long long t2 = idx / inner;
    int j        = (int)(t2 % K);
    long long o  = t2 / K;

    const float* base = in + o * (long long)n * inner + ii;
    int p = 2 * j - 1;
    float alo = 0.f, ahi = 0.f;
#pragma unroll
    for (int s = 0; s < 8; s++) {
        int q = p - s;
        if (q < 0) q += n; else if (q >= n) q -= n;
        float v = base[(long long)q * inner];
        alo += c_lo[s] * v;
        if (HI) ahi += c_hi[s] * v;
    }
    long long oi = (o * K + j) * (long long)inner + ii;
    olo[oi] = alo;
    if (HI) ohi[oi] = ahi;
}

// ---------------------------------------------------------------------------
// Inverse DWT along a middle axis. lo/hi viewed as (outer, K, inner),
// output (outer, nout, inner).
// y[i] = sum_{d=0..3} lo[i/2+1+d]*c_lo[2d+1-(i&1)] (+ hi[..]*c_hi[..]).
// For our (K, nout) pairs (23,37) and (37,64) the j-range never leaves [1,K-1].
// ---------------------------------------------------------------------------
template<bool HI>
__global__ void idwt_k(const float* __restrict__ lo, const float* __restrict__ hi,
                       float* __restrict__ out,
                       int K, int nout, int inner, long long total) {
    long long idx = (long long)blockIdx.x * blockDim.x + threadIdx.x;
    if (idx >= total) return;
    int ii       = (int)(idx % inner);
    long long t2 = idx / inner;
    int i        = (int)(t2 % nout);
    long long o  = t2 / nout;

    int js  = (i >> 1) + 1;
    int par = i & 1;                         // tap t = 2d + 1 - par
    const float* lb = lo + o * (long long)K * inner + ii;
    const float* hb = HI ? (hi + o * (long long)K * inner + ii) : lb;

    float acc = 0.f;
#pragma unroll
    for (int d = 0; d < 4; d++) {
        long long joff = (long long)(js + d) * inner;
        float fl = par ? c_lo[2 * d] : c_lo[2 * d + 1];
        acc += lb[joff] * fl;
        if (HI) {
            float fh = par ? c_hi[2 * d] : c_hi[2 * d + 1];
            acc += hb[joff] * fh;
        }
    }
    out[(o * nout + i) * (long long)inner + ii] = acc;
}

// ---------------------------------------------------------------------------
// Channel mix for one band: out[b,o,v] = sum_i in[b,i,v] * w[i,o,v]
// in (8,40,NV), w (40,40,NV), out (8,40,NV).
// Block = (32 voxels) x (8 o-rows); each thread keeps acc[5 o][8 b];
// input tile staged in 40KB smem; weights streamed coalesced (v fastest).
// ---------------------------------------------------------------------------
__global__ void chanmix_k(const float* __restrict__ in,
                          const float* __restrict__ w,
                          float* __restrict__ out) {
    __shared__ float s_in[320][32];
    int lane = threadIdx.x;       // voxel lane 0..31
    int ty   = threadIdx.y;       // 0..7
    int v    = blockIdx.x * 32 + lane;
    bool valid = v < NV;
    int vc = valid ? v : (NV - 1);   // clamp loads, guard stores

    for (int r = ty; r < 320; r += 8)            // r = b*40 + i
        s_in[r][lane] = in[(long long)r * NV + vc];
    __syncthreads();

    float acc[5][8];
#pragma unroll
    for (int a = 0; a < 5; a++)
#pragma unroll
        for (int b = 0; b < 8; b++) acc[a][b] = 0.f;

    for (int i = 0; i < 40; i++) {
        float xv[8];
#pragma unroll
        for (int b = 0; b < 8; b++) xv[b] = s_in[b * 40 + i][lane];
#pragma unroll
        for (int oo = 0; oo < 5; oo++) {
            int o = ty + oo * 8;
            float wv = w[((long long)i * 40 + o) * NV + vc];
#pragma unroll
            for (int b = 0; b < 8; b++) acc[oo][b] += xv[b] * wv;
        }
    }
    if (!valid) return;
#pragma unroll
    for (int oo = 0; oo < 5; oo++) {
        int o = ty + oo * 8;
#pragma unroll
        for (int b = 0; b < 8; b++)
            out[((long long)b * 40 + o) * NV + v] = acc[oo][b];
    }
}

// ---------------------------------------------------------------------------
extern "C" void kernel_launch(void* const* d_in, const int* in_sizes, int n_in,
                              void* d_out, int out_size) {
    const float* x = (const float*)d_in[0];
    float* out = (float*)d_out;

    float *b1, *b2;
    cudaGetSymbolAddress((void**)&b1, g_buf1);
    cudaGetSymbolAddress((void**)&b2, g_buf2);

    const long long S1  = 10075840LL;  // 320*23*37*37
    const long long S2  = 6263360LL;   // 320*23*23*37
    const long long SBl = 3893440LL;   // 320*23*23*23

    auto g = [](long long t) { return (unsigned)((t + 255) / 256); };

    // --- A: level-1 forward, lo only (details are zeroed in reconstruction) ---
    // (320,64,64,64) -x-> (320,37,64,64) -y-> (320,37,37,64) -z-> (320,37,37,37)
    dwt_k<false><<<g(48496640LL), 256>>>(x,  b1, nullptr, 64, 37, 4096, 48496640LL);
    dwt_k<false><<<g(28037120LL), 256>>>(b1, b2, nullptr, 64, 37, 64,   28037120LL);
    dwt_k<false><<<g(16208960LL), 256>>>(b2, b1, nullptr, 64, 37, 1,    16208960LL);

    // --- B: level-2 forward, full (8 bands). Slot order ends as 4z+2y+x. ---
    dwt_k<true><<<g(10075840LL), 256>>>(b1, b2, b2 + S1,      37, 23, 1369, 10075840LL);
    dwt_k<true><<<g(12526720LL), 256>>>(b2, b1, b1 + 2 * S2,  37, 23, 37,   12526720LL);
    dwt_k<true><<<g(15573760LL), 256>>>(b1, b2, b2 + 4 * SBl, 37, 23, 1,    15573760LL);

    // --- C: channel mix. weight k has bits (x,y,z) = k:(4x+2y+z); slot = 4z+2y+x.
    for (int k = 0; k < 8; k++) {
        int s = ((k & 1) << 2) | (k & 2) | ((k >> 2) & 1);
        chanmix_k<<<dim3((NV + 31) / 32), dim3(32, 8)>>>(
            b2 + (long long)s * SBl, (const float*)d_in[1 + k],
            b1 + (long long)s * SBl);
    }

    // --- D: level-2 inverse (full, 8 -> 4 -> 2 -> 1) ---
    idwt_k<true><<<g(25053440LL), 256>>>(b1, b1 + 4 * SBl, b2, 23, 37, 1,    25053440LL);
    idwt_k<true><<<g(20151680LL), 256>>>(b2, b2 + 2 * S2,  b1, 23, 37, 37,   20151680LL);
    idwt_k<true><<<g(16208960LL), 256>>>(b1, b1 + S1,      b2, 23, 37, 1369, 16208960LL);

    // --- E: level-1 inverse, lo only (all level-1 details zero) ---
    idwt_k<false><<<g(28037120LL), 256>>>(b2, nullptr, b1,  37, 64, 1,    28037120LL);
    idwt_k<false><<<g(48496640LL), 256>>>(b1, nullptr, b2,  37, 64, 64,   48496640LL);
    idwt_k<false><<<g(83886080LL), 256>>>(b2, nullptr, out, 37, 64, 4096, 83886080LL);
}

// round 2
// speedup vs baseline: 2.6387x; 2.6387x over previous
#include <cuda_runtime.h>

// ---------------------------------------------------------------------------
// WaveConv3d: 2-level db4 3D DWT (periodic pad 8) -> per-voxel channel mix on
// the 8 coarsest bands -> inverse DWT (level-1 details zero -> lo-only).
// All DWT/IDWT kernels fully unrolled via templates: compile-time indices,
// immediate filter constants, sliding-window data reuse.
// ---------------------------------------------------------------------------

#define NV 12167            // 23^3

#define FLO {-0.010597401784997278f,  0.032883011666982945f,  0.030841381835986965f, \
             -0.18703481171888114f,  -0.02798376941698385f,   0.6308807679295904f,  \
              0.7148465705525415f,    0.23037781330885523f}
#define FHI { 0.23037781330885523f,  -0.7148465705525415f,    0.6308807679295904f,  \
              0.02798376941698385f,  -0.18703481171888114f,  -0.030841381835986965f,\
              0.032883011666982945f,  0.010597401784997278f}

// Ping-pong scratch (max live tensor = 320*37*64*64 = 48,496,640 floats)
__device__ float g_buf1[48496640];
__device__ float g_buf2[48496640];

// ---------------------------------------------------------------------------
// Forward DWT along a strided axis. Tensor (outer, N, INNER) -> (outer, K, INNER).
// One thread per (o, ii): sliding 8-window, K outputs. Fully unrolled.
// ---------------------------------------------------------------------------
template<int N, int INNER, bool HI>
__global__ void dwt_s(const float* __restrict__ in, float* __restrict__ olo,
                      float* __restrict__ ohi, unsigned total) {
    constexpr int K = (N + 8) / 2 + 1;
    const float LO[8] = FLO;
    const float HIc[8] = FHI;
    unsigned g = blockIdx.x * blockDim.x + threadIdx.x;
    if (g >= total) return;
    unsigned ii = g % INNER;
    unsigned o  = g / INNER;
    const float* bp = in  + (size_t)o * (N * INNER) + ii;
    float*       lp = olo + (size_t)o * (K * INNER) + ii;
    float*       hp = HI ? ohi + (size_t)o * (K * INNER) + ii : nullptr;

    float w[8];
#pragma unroll
    for (int t = 0; t < 8; t++) w[t] = bp[(N - 8 + t) * INNER];

#pragma unroll
    for (int j = 0; j < K; j++) {
        float alo = 0.f, ahi = 0.f;
#pragma unroll
        for (int t = 0; t < 8; t++) {
            alo = fmaf(w[t], LO[7 - t], alo);
            if (HI) ahi = fmaf(w[t], HIc[7 - t], ahi);
        }
        lp[j * INNER] = alo;
        if (HI) hp[j * INNER] = ahi;
        if (j < K - 1) {
            constexpr int dummy = 0; (void)dummy;
            int q0 = (2 * j) % N;        // compile-time after unroll
            int q1 = (2 * j + 1) % N;
#pragma unroll
            for (int t = 0; t < 6; t++) w[t] = w[t + 2];
            w[6] = bp[q0 * INNER];
            w[7] = bp[q1 * INNER];
        }
    }
}

// ---------------------------------------------------------------------------
// Forward DWT along the contiguous axis (inner==1) via shared-memory tiles.
// Block: 256 threads, 32 rows of length N. Coalesced loads & stores.
// ---------------------------------------------------------------------------
template<int N, bool HI>
__global__ void dwt_c(const float* __restrict__ in, float* __restrict__ olo,
                      float* __restrict__ ohi) {
    constexpr int K = (N + 8) / 2 + 1;
    constexpr int R = 32;
    __shared__ float tile[R * N];
    const float LO[8] = FLO;
    const float HIc[8] = FHI;
    unsigned tid = threadIdx.x;
    size_t row0 = (size_t)blockIdx.x * R;
    const float* gp = in + row0 * N;
#pragma unroll 4
    for (int t = tid; t < R * N; t += 256) tile[t] = gp[t];
    __syncthreads();

    int warp = tid >> 5, lane = tid & 31;
#pragma unroll
    for (int rr = 0; rr < 4; rr++) {
        int r = warp * 4 + rr;
        const float* tp = tile + r * N;
        float* lp = olo + (row0 + r) * K;
        float* hp = HI ? ohi + (row0 + r) * K : nullptr;
        for (int j = lane; j < K; j += 32) {
            int p = 2 * j - 1;
            float alo = 0.f, ahi = 0.f;
#pragma unroll
            for (int s = 0; s < 8; s++) {
                int q = p - s;
                if (q < 0) q += N; else if (q >= N) q -= N;
                float v = tp[q];
                alo = fmaf(LO[s], v, alo);
                if (HI) ahi = fmaf(HIc[s], v, ahi);
            }
            lp[j] = alo;
            if (HI) hp[j] = ahi;
        }
    }
}

// ---------------------------------------------------------------------------
// Inverse DWT along a strided axis. (outer, K, INNER) -> (outer, NOUT, INNER).
// y[i] = sum_d lo[i/2+1+d]*LO[2d+1-(i&1)] (+ hi*HI[...]). Indices never wrap.
// One thread per (o, ii): sliding 4-window (lo + optional hi), NOUT outputs.
// ---------------------------------------------------------------------------
template<int K, int NOUT, int INNER, bool HI>
__global__ void idwt_s(const float* __restrict__ lo, const float* __restrict__ hi,
                       float* __restrict__ out, unsigned total) {
    const float LO[8] = FLO;
    const float HIc[8] = FHI;
    unsigned g = blockIdx.x * blockDim.x + threadIdx.x;
    if (g >= total) return;
    unsigned ii = g % INNER;
    unsigned o  = g / INNER;
    const float* lp = lo + (size_t)o * (K * INNER) + ii;
    const float* hp = HI ? hi + (size_t)o * (K * INNER) + ii : lp;
    float*       op = out + (size_t)o * (NOUT * INNER) + ii;

    float wl[4], wh[4];
#pragma unroll
    for (int d = 0; d < 4; d++) {
        wl[d] = lp[(1 + d) * INNER];
        if (HI) wh[d] = hp[(1 + d) * INNER];
    }
#pragma unroll
    for (int i = 0; i < NOUT; i++) {
        constexpr int P = 0; (void)P;
        const int par = i & 1;           // compile-time after unroll
        float acc = 0.f;
#pragma unroll
        for (int d = 0; d < 4; d++) {
            acc = fmaf(wl[d], LO[2 * d + 1 - par], acc);
            if (HI) acc = fmaf(wh[d], HIc[2 * d + 1 - par], acc);
        }
        op[i * INNER] = acc;
        if (par && (i + 1 < NOUT)) {
            int jn = i / 2 + 5;          // compile-time
#pragma unroll
            for (int d = 0; d < 3; d++) {
                wl[d] = wl[d + 1];
                if (HI) wh[d] = wh[d + 1];
            }
            wl[3] = lp[jn * INNER];
            if (HI) wh[3] = hp[jn * INNER];
        }
    }
}

// ---------------------------------------------------------------------------
// Inverse DWT along the contiguous axis via shared-memory tiles.
// ---------------------------------------------------------------------------
template<int K, int NOUT, bool HI>
__global__ void idwt_c(const float* __restrict__ lo, const float* __restrict__ hi,
                       float* __restrict__ out) {
    constexpr int R = 32;
    __shared__ float tl[R * K];
    __shared__ float th[HI ? R * K : 1];
    const float LO[8] = FLO;
    const float HIc[8] = FHI;
    unsigned tid = threadIdx.x;
    size_t row0 = (size_t)blockIdx.x * R;
    const float* glp = lo + row0 * K;
#pragma unroll 4
    for (int t = tid; t < R * K; t += 256) tl[t] = glp[t];
    if (HI) {
        const float* ghp = hi + row0 * K;
#pragma unroll 4
        for (int t = tid; t < R * K; t += 256) th[t] = ghp[t];
    }
    __syncthreads();

    int warp = tid >> 5, lane = tid & 31;
#pragma unroll
    for (int rr = 0; rr < 4; rr++) {
        int r = warp * 4 + rr;
        const float* tlp = tl + r * K;
        const float* thp = HI ? th + r * K : tlp;
        float* op = out + (row0 + r) * NOUT;
        for (int i = lane; i < NOUT; i += 32) {
            int js = (i >> 1) + 1;
            int par = i & 1;
            float acc = 0.f;
#pragma unroll
            for (int d = 0; d < 4; d++) {
                float fl = par ? LO[2 * d] : LO[2 * d + 1];
                acc = fmaf(tlp[js + d], fl, acc);
                if (HI) {
                    float fh = par ? HIc[2 * d] : HIc[2 * d + 1];
                    acc = fmaf(thp[js + d], fh, acc);
                }
            }
            op[i] = acc;
        }
    }
}

// ---------------------------------------------------------------------------
// Channel mix for one band: out[b,o,v] = sum_i in[b,i,v] * w[i,o,v]
// ---------------------------------------------------------------------------
__global__ void chanmix_k(const float* __restrict__ in,
                          const float* __restrict__ w,
                          float* __restrict__ out) {
    __shared__ float s_in[320][32];
    int lane = threadIdx.x;
    int ty   = threadIdx.y;
    int v    = blockIdx.x * 32 + lane;
    bool valid = v < NV;
    int vc = valid ? v : (NV - 1);

    for (int r = ty; r < 320; r += 8)
        s_in[r][lane] = in[(long long)r * NV + vc];
    __syncthreads();

    float acc[5][8];
#pragma unroll
    for (int a = 0; a < 5; a++)
#pragma unroll
        for (int b = 0; b < 8; b++) acc[a][b] = 0.f;

    for (int i = 0; i < 40; i++) {
        float xv[8];
#pragma unroll
        for (int b = 0; b < 8; b++) xv[b] = s_in[b * 40 + i][lane];
#pragma unroll
        for (int oo = 0; oo < 5; oo++) {
            int o = ty + oo * 8;
            float wv = w[((long long)i * 40 + o) * NV + vc];
#pragma unroll
            for (int b = 0; b < 8; b++) acc[oo][b] += xv[b] * wv;
        }
    }
    if (!valid) return;
#pragma unroll
    for (int oo = 0; oo < 5; oo++) {
        int o = ty + oo * 8;
#pragma unroll
        for (int b = 0; b < 8; b++)
            out[((long long)b * 40 + o) * NV + v] = acc[oo][b];
    }
}

// ---------------------------------------------------------------------------
extern "C" void kernel_launch(void* const* d_in, const int* in_sizes, int n_in,
                              void* d_out, int out_size) {
    const float* x = (const float*)d_in[0];
    float* out = (float*)d_out;

    float *b1, *b2;
    cudaGetSymbolAddress((void**)&b1, g_buf1);
    cudaGetSymbolAddress((void**)&b2, g_buf2);

    const long long S1  = 10075840LL;  // 320*23*37*37
    const long long S2  = 6263360LL;   // 320*23*23*37
    const long long SBl = 3893440LL;   // 320*23*23*23

    auto g = [](unsigned t) { return (t + 255u) / 256u; };

    // --- A: level-1 forward, lo only ---------------------------------------
    // (320,64,64,64) -x-> (320,37,64,64) -y-> (320,37,37,64) -z-> (320,37,37,37)
    { unsigned T = 320u * 4096u;
      dwt_s<64, 4096, false><<<g(T), 256>>>(x,  b1, nullptr, T); }
    { unsigned T = 11840u * 64u;
      dwt_s<64, 64,   false><<<g(T), 256>>>(b1, b2, nullptr, T); }
    dwt_c<64, false><<<438080 / 32, 256>>>(b2, b1, nullptr);

    // --- B: level-2 forward, full (8 bands; final slot = 4z + 2y + x) ------
    { unsigned T = 320u * 1369u;
      dwt_s<37, 1369, true><<<g(T), 256>>>(b1, b2, b2 + S1, T); }
    { unsigned T = 14720u * 37u;
      dwt_s<37, 37,   true><<<g(T), 256>>>(b2, b1, b1 + 2 * S2, T); }
    dwt_c<37, true><<<677120 / 32, 256>>>(b1, b2, b2 + 4 * SBl);

    // --- C: channel mix. weight k bits (x,y,z) = k:(4x+2y+z); slot = 4z+2y+x.
    for (int k = 0; k < 8; k++) {
        int s = ((k & 1) << 2) | (k & 2) | ((k >> 2) & 1);
        chanmix_k<<<dim3((NV + 31) / 32), dim3(32, 8)>>>(
            b2 + (long long)s * SBl, (const float*)d_in[1 + k],
            b1 + (long long)s * SBl);
    }

    // --- D: level-2 inverse (8 -> 4 -> 2 -> 1) ------------------------------
    idwt_c<23, 37, true><<<677120 / 32, 256>>>(b1, b1 + 4 * SBl, b2);
    { unsigned T = 14720u * 37u;
      idwt_s<23, 37, 37,   true><<<g(T), 256>>>(b2, b2 + 2 * S2, b1, T); }
    { unsigned T = 320u * 1369u;
      idwt_s<23, 37, 1369, true><<<g(T), 256>>>(b1, b1 + S1, b2, T); }

    // --- E: level-1 inverse, lo only ----------------------------------------
    idwt_c<37, 64, false><<<438080 / 32, 256>>>(b2, nullptr, b1);
    { unsigned T = 11840u * 64u;
      idwt_s<37, 64, 64,   false><<<g(T), 256>>>(b1, nullptr, b2, T); }
    { unsigned T = 320u * 4096u;
      idwt_s<37, 64, 4096, false><<<g(T), 256>>>(b2, nullptr, out, T); }
}

// round 4
// speedup vs baseline: 3.0692x; 1.1631x over previous
#include <cuda_runtime.h>

// ---------------------------------------------------------------------------
// WaveConv3d: 2-level db4 3D DWT (periodic, pad 8) -> per-voxel channel mix on
// the 8 coarsest bands -> inverse DWT (level-1 details zero -> lo-only).
// R4: R3 design with the forward-wrap bug fixed (q can exceed N-1 for high j;
// wrap BOTH directions in the fused forward kernels).
// ---------------------------------------------------------------------------

#define NV 12167            // 23^3

#define FLO {-0.010597401784997278f,  0.032883011666982945f,  0.030841381835986965f, \
             -0.18703481171888114f,  -0.02798376941698385f,   0.6308807679295904f,  \
              0.7148465705525415f,    0.23037781330885523f}
#define FHI { 0.23037781330885523f,  -0.7148465705525415f,    0.6308807679295904f,  \
              0.02798376941698385f,  -0.18703481171888114f,  -0.030841381835986965f,\
              0.032883011666982945f,  0.010597401784997278f}

// Scratch (max live = 8 bands * 320*23^3 = 31.1M floats)
__device__ float g_buf1[31147520];
__device__ float g_buf2[31147520];

// ---------------------------------------------------------------------------
// Forward DWT along a strided axis (x-pass). (outer, N, INNER) -> (outer, K, INNER).
// ---------------------------------------------------------------------------
template<int N, int INNER, bool HI>
__global__ void dwt_s(const float* __restrict__ in, float* __restrict__ olo,
                      float* __restrict__ ohi, unsigned total) {
    constexpr int K = (N + 8) / 2 + 1;
    const float LO[8] = FLO;
    const float HIc[8] = FHI;
    unsigned g = blockIdx.x * blockDim.x + threadIdx.x;
    if (g >= total) return;
    unsigned ii = g % INNER;
    unsigned o  = g / INNER;
    const float* bp = in  + (size_t)o * (N * INNER) + ii;
    float*       lp = olo + (size_t)o * (K * INNER) + ii;
    float*       hp = HI ? ohi + (size_t)o * (K * INNER) + ii : nullptr;

    float w[8];
#pragma unroll
    for (int t = 0; t < 8; t++) w[t] = bp[(N - 8 + t) * INNER];

#pragma unroll
    for (int j = 0; j < K; j++) {
        float alo = 0.f, ahi = 0.f;
#pragma unroll
        for (int t = 0; t < 8; t++) {
            alo = fmaf(w[t], LO[7 - t], alo);
            if (HI) ahi = fmaf(w[t], HIc[7 - t], ahi);
        }
        lp[j * INNER] = alo;
        if (HI) hp[j * INNER] = ahi;
        if (j < K - 1) {
            int q0 = (2 * j) % N;        // compile-time after unroll
            int q1 = (2 * j + 1) % N;
#pragma unroll
            for (int t = 0; t < 6; t++) w[t] = w[t + 2];
            w[6] = bp[q0 * INNER];
            w[7] = bp[q1 * INNER];
        }
    }
}

// ---------------------------------------------------------------------------
// Inverse DWT along a strided axis (x-pass). Indices never wrap for our sizes.
// ---------------------------------------------------------------------------
template<int K, int NOUT, int INNER, bool HI>
__global__ void idwt_s(const float* __restrict__ lo, const float* __restrict__ hi,
                       float* __restrict__ out, unsigned total) {
    const float LO[8] = FLO;
    const float HIc[8] = FHI;
    unsigned g = blockIdx.x * blockDim.x + threadIdx.x;
    if (g >= total) return;
    unsigned ii = g % INNER;
    unsigned o  = g / INNER;
    const float* lp = lo + (size_t)o * (K * INNER) + ii;
    const float* hp = HI ? hi + (size_t)o * (K * INNER) + ii : lp;
    float*       op = out + (size_t)o * (NOUT * INNER) + ii;

    float wl[4], wh[4];
#pragma unroll
    for (int d = 0; d < 4; d++) {
        wl[d] = lp[(1 + d) * INNER];
        if (HI) wh[d] = hp[(1 + d) * INNER];
    }
#pragma unroll
    for (int i = 0; i < NOUT; i++) {
        const int par = i & 1;           // compile-time after unroll
        float acc = 0.f;
#pragma unroll
        for (int d = 0; d < 4; d++) {
            acc = fmaf(wl[d], LO[2 * d + 1 - par], acc);
            if (HI) acc = fmaf(wh[d], HIc[2 * d + 1 - par], acc);
        }
        op[i * INNER] = acc;
        if (par && (i + 1 < NOUT)) {
            int jn = i / 2 + 5;          // compile-time
#pragma unroll
            for (int d = 0; d < 3; d++) {
                wl[d] = wl[d + 1];
                if (HI) wh[d] = wh[d + 1];
            }
            wl[3] = lp[jn * INNER];
            if (HI) wh[3] = hp[jn * INNER];
        }
    }
}

// ---------------------------------------------------------------------------
// Level-1 forward, fused y+z, lo-only. One block per (bc, x) slice:
// 64x64 -> (y-DWT) 37x64 -> (z-DWT) 37x37.
// ---------------------------------------------------------------------------
__global__ void f1_yz(const float* __restrict__ in, float* __restrict__ out) {
    __shared__ float s0[64 * 64];
    __shared__ float s1[37 * 64];
    const float LO[8] = FLO;
    unsigned tid = threadIdx.x;
    size_t blk = blockIdx.x;
    const float* gp = in + blk * 4096;
#pragma unroll 4
    for (int t = tid; t < 4096; t += 256) s0[t] = gp[t];
    __syncthreads();
    for (int t = tid; t < 37 * 64; t += 256) {       // y-DWT
        int z = t & 63, j = t >> 6;
        int p = 2 * j - 1;
        float a = 0.f;
#pragma unroll
        for (int s = 0; s < 8; s++) {
            int q = (p - s) & 63;                     // two-sided wrap, N=64
            a = fmaf(LO[s], s0[q * 64 + z], a);
        }
        s1[j * 64 + z] = a;
    }
    __syncthreads();
    float* op = out + blk * 1369;
    for (int t = tid; t < 1369; t += 256) {          // z-DWT
        int zp = t % 37, y = t / 37;
        int p = 2 * zp - 1;
        float a = 0.f;
#pragma unroll
        for (int s = 0; s < 8; s++) {
            int q = (p - s) & 63;                     // FIX: was one-sided
            a = fmaf(LO[s], s1[y * 64 + q], a);
        }
        op[t] = a;
    }
}

// ---------------------------------------------------------------------------
// Level-2 forward, fused y+z, full (4 yz-bands). One block per (bc, x) slice:
// 37x37 -> (y lo/hi) 2x 23x37 -> (z lo/hi) 4x 23x23.
// ---------------------------------------------------------------------------
__global__ void f2_yz(const float* __restrict__ in, float* __restrict__ out,
                      long long S2) {
    __shared__ float s0[37 * 37];
    __shared__ float sl[23 * 37];
    __shared__ float sh[23 * 37];
    const float LO[8] = FLO;
    const float HIc[8] = FHI;
    unsigned tid = threadIdx.x;
    size_t blk = blockIdx.x;
    const float* gp = in + blk * 1369;
#pragma unroll 3
    for (int t = tid; t < 1369; t += 256) s0[t] = gp[t];
    __syncthreads();
    for (int t = tid; t < 23 * 37; t += 256) {       // y-DWT lo+hi
        int z = t % 37, j = t / 37;
        int p = 2 * j - 1;
        float alo = 0.f, ahi = 0.f;
#pragma unroll
        for (int s = 0; s < 8; s++) {
            int q = p - s;
            if (q < 0) q += 37; else if (q >= 37) q -= 37;   // FIX: two-sided
            float v = s0[q * 37 + z];
            alo = fmaf(LO[s], v, alo);
            ahi = fmaf(HIc[s], v, ahi);
        }
        sl[j * 37 + z] = alo;
        sh[j * 37 + z] = ahi;
    }
    __syncthreads();
    for (int t = tid; t < 529; t += 256) {           // z-DWT on both
        int zp = t % 23, y = t / 23;
        int p = 2 * zp - 1;
        float ll = 0.f, lh = 0.f, hl = 0.f, hh = 0.f;
#pragma unroll
        for (int s = 0; s < 8; s++) {
            int q = p - s;
            if (q < 0) q += 37; else if (q >= 37) q -= 37;   // FIX: two-sided
            float vl = sl[y * 37 + q], vh = sh[y * 37 + q];
            ll = fmaf(LO[s], vl, ll);  lh = fmaf(HIc[s], vl, lh);
            hl = fmaf(LO[s], vh, hl);  hh = fmaf(HIc[s], vh, hh);
        }
        size_t base = blk * 529 + t;
        out[base]          = ll;
        out[S2 + base]     = lh;
        out[2 * S2 + base] = hl;
        out[3 * S2 + base] = hh;
    }
}

// ---------------------------------------------------------------------------
// Level-2 inverse, fused z+y, full. One block per (bc, x) slice:
// 4x 23x23 -> (z-IDWT pairs) 2x 23x37 -> (y-IDWT) 37x37. (No wrap needed.)
// ---------------------------------------------------------------------------
__global__ void i2_yz(const float* __restrict__ in, float* __restrict__ out,
                      long long S2) {
    __shared__ float si[4 * 529];
    __shared__ float sl[23 * 37];
    __shared__ float sh[23 * 37];
    const float LO[8] = FLO;
    const float HIc[8] = FHI;
    unsigned tid = threadIdx.x;
    size_t blk = blockIdx.x;
    for (int t = tid; t < 4 * 529; t += 256) {
        int slot = t / 529, r = t % 529;
        si[t] = in[(size_t)slot * S2 + blk * 529 + r];
    }
    __syncthreads();
    for (int t = tid; t < 23 * 37; t += 256) {       // z-IDWT (both dy rows)
        int i = t % 37, y = t / 37;
        int js = (i >> 1) + 1, par = i & 1;
        float a0 = 0.f, a1 = 0.f;
#pragma unroll
        for (int d = 0; d < 4; d++) {
            float fl = par ? LO[2 * d] : LO[2 * d + 1];
            float fh = par ? HIc[2 * d] : HIc[2 * d + 1];
            int q = y * 23 + js + d;
            a0 = fmaf(si[q],           fl, a0);
            a0 = fmaf(si[529 + q],     fh, a0);
            a1 = fmaf(si[2 * 529 + q], fl, a1);
            a1 = fmaf(si[3 * 529 + q], fh, a1);
        }
        sl[y * 37 + i] = a0;
        sh[y * 37 + i] = a1;
    }
    __syncthreads();
    float* op = out + blk * 1369;
    for (int t = tid; t < 1369; t += 256) {          // y-IDWT
        int z = t % 37, yo = t / 37;
        int js = (yo >> 1) + 1, par = yo & 1;
        float a = 0.f;
#pragma unroll
        for (int d = 0; d < 4; d++) {
            float fl = par ? LO[2 * d] : LO[2 * d + 1];
            float fh = par ? HIc[2 * d] : HIc[2 * d + 1];
            a = fmaf(sl[(js + d) * 37 + z], fl, a);
            a = fmaf(sh[(js + d) * 37 + z], fh, a);
        }
        op[t] = a;
    }
}

// ---------------------------------------------------------------------------
// Level-1 inverse, fused z+y, lo-only. One block per (bc, x) slice:
// 37x37 -> (z-IDWT) 37x64 -> (y-IDWT) 64x64. (No wrap needed.)
// ---------------------------------------------------------------------------
__global__ void i1_yz(const float* __restrict__ in, float* __restrict__ out) {
    __shared__ float s0[37 * 37];
    __shared__ float s1[37 * 64];
    const float LO[8] = FLO;
    unsigned tid = threadIdx.x;
    size_t blk = blockIdx.x;
    const float* gp = in + blk * 1369;
#pragma unroll 3
    for (int t = tid; t < 1369; t += 256) s0[t] = gp[t];
    __syncthreads();
    for (int t = tid; t < 37 * 64; t += 256) {       // z-IDWT
        int i = t & 63, y = t >> 6;
        int js = (i >> 1) + 1, par = i & 1;
        float a = 0.f;
#pragma unroll
        for (int d = 0; d < 4; d++) {
            float fl = par ? LO[2 * d] : LO[2 * d + 1];
            a = fmaf(s0[y * 37 + js + d], fl, a);
        }
        s1[y * 64 + i] = a;
    }
    __syncthreads();
    float* op = out + blk * 4096;
#pragma unroll 4
    for (int t = tid; t < 4096; t += 256) {          // y-IDWT
        int z = t & 63, yo = t >> 6;
        int js = (yo >> 1) + 1, par = yo & 1;
        float a = 0.f;
#pragma unroll
        for (int d = 0; d < 4; d++) {
            float fl = par ? LO[2 * d] : LO[2 * d + 1];
            a = fmaf(s1[(js + d) * 64 + z], fl, a);
        }
        op[t] = a;
    }
}

// ---------------------------------------------------------------------------
// Channel mix for one band: out[b,o,v] = sum_i in[b,i,v] * w[i,o,v]
// ---------------------------------------------------------------------------
__global__ void chanmix_k(const float* __restrict__ in,
                          const float* __restrict__ w,
                          float* __restrict__ out) {
    __shared__ float s_in[320][32];
    int lane = threadIdx.x;
    int ty   = threadIdx.y;
    int v    = blockIdx.x * 32 + lane;
    bool valid = v < NV;
    int vc = valid ? v : (NV - 1);

    for (int r = ty; r < 320; r += 8)
        s_in[r][lane] = in[(long long)r * NV + vc];
    __syncthreads();

    float acc[5][8];
#pragma unroll
    for (int a = 0; a < 5; a++)
#pragma unroll
        for (int b = 0; b < 8; b++) acc[a][b] = 0.f;

    for (int i = 0; i < 40; i++) {
        float xv[8];
#pragma unroll
        for (int b = 0; b < 8; b++) xv[b] = s_in[b * 40 + i][lane];
#pragma unroll
        for (int oo = 0; oo < 5; oo++) {
            int o = ty + oo * 8;
            float wv = w[((long long)i * 40 + o) * NV + vc];
#pragma unroll
            for (int b = 0; b < 8; b++) acc[oo][b] += xv[b] * wv;
        }
    }
    if (!valid) return;
#pragma unroll
    for (int oo = 0; oo < 5; oo++) {
        int o = ty + oo * 8;
#pragma unroll
        for (int b = 0; b < 8; b++)
            out[((long long)b * 40 + o) * NV + v] = acc[oo][b];
    }
}

// ---------------------------------------------------------------------------
extern "C" void kernel_launch(void* const* d_in, const int* in_sizes, int n_in,
                              void* d_out, int out_size) {
    const float* x = (const float*)d_in[0];
    float* out = (float*)d_out;

    float *b1, *b2;
    cudaGetSymbolAddress((void**)&b1, g_buf1);
    cudaGetSymbolAddress((void**)&b2, g_buf2);

    const long long S2  = 6263360LL;   // 320*37*23*23 (per yz-band volume)
    const long long SBl = 3893440LL;   // 320*23*23*23 (per final band volume)

    auto g = [](unsigned t) { return (t + 255u) / 256u; };

    // --- Level-1 forward: fused yz (lo), then x (lo) ------------------------
    f1_yz<<<320 * 64, 256>>>(x, b1);                        // -> (320,64,37,37)
    { unsigned T = 320u * 1369u;                            // -> (320,37,37,37)
      dwt_s<64, 1369, false><<<g(T), 256>>>(b1, b2, nullptr, T); }

    // --- Level-2 forward: fused yz (4 bands), then x (lo+hi over all 4) -----
    f2_yz<<<320 * 37, 256>>>(b2, b1, S2);                   // -> 4x(320,37,23,23)
    { unsigned T = 1280u * 529u;                            // -> 8x(320,23,23,23)
      dwt_s<37, 529, true><<<g(T), 256>>>(b1, b2, b2 + 4 * SBl, T); }

    // --- Channel mix: band slot == weight index k (= 4dx+2dy+dz) ------------
    for (int k = 0; k < 8; k++)
        chanmix_k<<<dim3((NV + 31) / 32), dim3(32, 8)>>>(
            b2 + (long long)k * SBl, (const float*)d_in[1 + k],
            b1 + (long long)k * SBl);

    // --- Level-2 inverse: x (lo+hi over all 4), then fused zy ---------------
    { unsigned T = 1280u * 529u;                            // -> 4x(320,37,23,23)
      idwt_s<23, 37, 529, true><<<g(T), 256>>>(b1, b1 + 4 * SBl, b2, T); }
    i2_yz<<<320 * 37, 256>>>(b2, b1, S2);                   // -> (320,37,37,37)

    // --- Level-1 inverse: x (lo), then fused zy (lo) -------------------------
    { unsigned T = 320u * 1369u;                            // -> (320,64,37,37)
      idwt_s<37, 64, 1369, false><<<g(T), 256>>>(b1, nullptr, b2, T); }
    i1_yz<<<320 * 64, 256>>>(b2, out);                      // -> (320,64,64,64)
}

// round 5
// speedup vs baseline: 3.5992x; 1.1727x over previous
#include <cuda_runtime.h>

// ---------------------------------------------------------------------------
// WaveConv3d: 2-level db4 3D DWT (periodic, pad 8) -> per-voxel channel mix on
// the 8 coarsest bands -> inverse DWT (level-1 details zero -> lo-only).
// R5: single merged chanmix launch (+unroll), paired-output fused yz kernels
// (shared 8/10-tap windows halve LDS), padded smem rows to kill conflicts.
// ---------------------------------------------------------------------------

#define NV 12167            // 23^3

#define FLO {-0.010597401784997278f,  0.032883011666982945f,  0.030841381835986965f, \
             -0.18703481171888114f,  -0.02798376941698385f,   0.6308807679295904f,  \
              0.7148465705525415f,    0.23037781330885523f}
#define FHI { 0.23037781330885523f,  -0.7148465705525415f,    0.6308807679295904f,  \
              0.02798376941698385f,  -0.18703481171888114f,  -0.030841381835986965f,\
              0.032883011666982945f,  0.010597401784997278f}

// Scratch (max live = 8 bands * 320*23^3 = 31.1M floats)
__device__ float g_buf1[31147520];
__device__ float g_buf2[31147520];

// ---------------------------------------------------------------------------
// Forward DWT along a strided axis (x-pass). (outer, N, INNER) -> (outer, K, INNER).
// Near LTS-cap in R4 profile; unchanged.
// ---------------------------------------------------------------------------
template<int N, int INNER, bool HI>
__global__ void dwt_s(const float* __restrict__ in, float* __restrict__ olo,
                      float* __restrict__ ohi, unsigned total) {
    constexpr int K = (N + 8) / 2 + 1;
    const float LO[8] = FLO;
    const float HIc[8] = FHI;
    unsigned g = blockIdx.x * blockDim.x + threadIdx.x;
    if (g >= total) return;
    unsigned ii = g % INNER;
    unsigned o  = g / INNER;
    const float* bp = in  + (size_t)o * (N * INNER) + ii;
    float*       lp = olo + (size_t)o * (K * INNER) + ii;
    float*       hp = HI ? ohi + (size_t)o * (K * INNER) + ii : nullptr;

    float w[8];
#pragma unroll
    for (int t = 0; t < 8; t++) w[t] = bp[(N - 8 + t) * INNER];

#pragma unroll
    for (int j = 0; j < K; j++) {
        float alo = 0.f, ahi = 0.f;
#pragma unroll
        for (int t = 0; t < 8; t++) {
            alo = fmaf(w[t], LO[7 - t], alo);
            if (HI) ahi = fmaf(w[t], HIc[7 - t], ahi);
        }
        lp[j * INNER] = alo;
        if (HI) hp[j * INNER] = ahi;
        if (j < K - 1) {
            int q0 = (2 * j) % N;
            int q1 = (2 * j + 1) % N;
#pragma unroll
            for (int t = 0; t < 6; t++) w[t] = w[t + 2];
            w[6] = bp[q0 * INNER];
            w[7] = bp[q1 * INNER];
        }
    }
}

// ---------------------------------------------------------------------------
// Inverse DWT along a strided axis (x-pass). Indices never wrap. Unchanged.
// ---------------------------------------------------------------------------
template<int K, int NOUT, int INNER, bool HI>
__global__ void idwt_s(const float* __restrict__ lo, const float* __restrict__ hi,
                       float* __restrict__ out, unsigned total) {
    const float LO[8] = FLO;
    const float HIc[8] = FHI;
    unsigned g = blockIdx.x * blockDim.x + threadIdx.x;
    if (g >= total) return;
    unsigned ii = g % INNER;
    unsigned o  = g / INNER;
    const float* lp = lo + (size_t)o * (K * INNER) + ii;
    const float* hp = HI ? hi + (size_t)o * (K * INNER) + ii : lp;
    float*       op = out + (size_t)o * (NOUT * INNER) + ii;

    float wl[4], wh[4];
#pragma unroll
    for (int d = 0; d < 4; d++) {
        wl[d] = lp[(1 + d) * INNER];
        if (HI) wh[d] = hp[(1 + d) * INNER];
    }
#pragma unroll
    for (int i = 0; i < NOUT; i++) {
        const int par = i & 1;
        float acc = 0.f;
#pragma unroll
        for (int d = 0; d < 4; d++) {
            acc = fmaf(wl[d], LO[2 * d + 1 - par], acc);
            if (HI) acc = fmaf(wh[d], HIc[2 * d + 1 - par], acc);
        }
        op[i * INNER] = acc;
        if (par && (i + 1 < NOUT)) {
            int jn = i / 2 + 5;
#pragma unroll
            for (int d = 0; d < 3; d++) {
                wl[d] = wl[d + 1];
                if (HI) wh[d] = wh[d + 1];
            }
            wl[3] = lp[jn * INNER];
            if (HI) wh[3] = hp[jn * INNER];
        }
    }
}

// ---------------------------------------------------------------------------
// Level-1 forward, fused y+z, lo-only, paired outputs. Block per (bc,x) slice:
// 64x64 -> (y-DWT) 37x64 -> (z-DWT) 37x37.  s1 row padded to 65.
// ---------------------------------------------------------------------------
__global__ void f1_yz(const float* __restrict__ in, float* __restrict__ out) {
    __shared__ float s0[64 * 64];
    __shared__ float s1[37 * 65];
    const float LO[8] = FLO;
    unsigned tid = threadIdx.x;
    size_t blk = blockIdx.x;
    const float* gp = in + blk * 4096;
#pragma unroll 4
    for (int t = tid; t < 4096; t += 256) s0[t] = gp[t];
    __syncthreads();
    // y-DWT: pairs (j0=2jp, j0+1); shared 10-tap window. 19 pairs x 64 z.
    for (int u = tid; u < 19 * 64; u += 256) {
        int z = u & 63, jp = u >> 6;
        float w[10];
#pragma unroll
        for (int t = 0; t < 10; t++) {
            int q = (4 * jp - 8 + t) & 63;
            w[t] = s0[q * 64 + z];
        }
        float a0 = 0.f, a1 = 0.f;
#pragma unroll
        for (int s = 0; s < 8; s++) {
            a0 = fmaf(LO[s], w[7 - s], a0);
            a1 = fmaf(LO[s], w[9 - s], a1);
        }
        s1[(2 * jp) * 65 + z] = a0;
        if (2 * jp + 1 < 37) s1[(2 * jp + 1) * 65 + z] = a1;
    }
    __syncthreads();
    float* op = out + blk * 1369;
    // z-DWT: pairs. 37 y x 19 pairs.
    for (int u = tid; u < 37 * 19; u += 256) {
        int ph = u % 19, y = u / 19;
        float w[10];
#pragma unroll
        for (int t = 0; t < 10; t++) {
            int q = (4 * ph - 8 + t) & 63;
            w[t] = s1[y * 65 + q];
        }
        float a0 = 0.f, a1 = 0.f;
#pragma unroll
        for (int s = 0; s < 8; s++) {
            a0 = fmaf(LO[s], w[7 - s], a0);
            a1 = fmaf(LO[s], w[9 - s], a1);
        }
        op[y * 37 + 2 * ph] = a0;
        if (2 * ph + 1 < 37) op[y * 37 + 2 * ph + 1] = a1;
    }
}

// ---------------------------------------------------------------------------
// Level-2 forward, fused y+z, full (4 yz-bands), paired outputs.
// 37x37 -> (y lo/hi) 2x 23x37 -> (z lo/hi) 4x 23x23.
// ---------------------------------------------------------------------------
__global__ void f2_yz(const float* __restrict__ in, float* __restrict__ out,
                      long long S2) {
    __shared__ float s0[37 * 37];
    __shared__ float sl[23 * 37];
    __shared__ float sh[23 * 37];
    const float LO[8] = FLO;
    const float HIc[8] = FHI;
    unsigned tid = threadIdx.x;
    size_t blk = blockIdx.x;
    const float* gp = in + blk * 1369;
#pragma unroll 3
    for (int t = tid; t < 1369; t += 256) s0[t] = gp[t];
    __syncthreads();
    // y-DWT lo+hi, paired: 12 pairs x 37 z.
    for (int u = tid; u < 12 * 37; u += 256) {
        int z = u % 37, jp = u / 37;
        float w[10];
#pragma unroll
        for (int t = 0; t < 10; t++) {
            int q = 4 * jp - 8 + t;
            if (q < 0) q += 37; else if (q >= 37) q -= 37;
            w[t] = s0[q * 37 + z];
        }
        float l0 = 0.f, h0 = 0.f, l1 = 0.f, h1 = 0.f;
#pragma unroll
        for (int s = 0; s < 8; s++) {
            l0 = fmaf(LO[s],  w[7 - s], l0);
            h0 = fmaf(HIc[s], w[7 - s], h0);
            l1 = fmaf(LO[s],  w[9 - s], l1);
            h1 = fmaf(HIc[s], w[9 - s], h1);
        }
        sl[(2 * jp) * 37 + z] = l0;
        sh[(2 * jp) * 37 + z] = h0;
        if (2 * jp + 1 < 23) {
            sl[(2 * jp + 1) * 37 + z] = l1;
            sh[(2 * jp + 1) * 37 + z] = h1;
        }
    }
    __syncthreads();
    // z-DWT on both, paired: 23 y x 12 pairs.
    for (int u = tid; u < 23 * 12; u += 256) {
        int ph = u % 12, y = u / 12;
        float wl[10], wh[10];
#pragma unroll
        for (int t = 0; t < 10; t++) {
            int q = 4 * ph - 8 + t;
            if (q < 0) q += 37; else if (q >= 37) q -= 37;
            wl[t] = sl[y * 37 + q];
            wh[t] = sh[y * 37 + q];
        }
        float ll0 = 0.f, lh0 = 0.f, hl0 = 0.f, hh0 = 0.f;
        float ll1 = 0.f, lh1 = 0.f, hl1 = 0.f, hh1 = 0.f;
#pragma unroll
        for (int s = 0; s < 8; s++) {
            ll0 = fmaf(LO[s],  wl[7 - s], ll0);  lh0 = fmaf(HIc[s], wl[7 - s], lh0);
            hl0 = fmaf(LO[s],  wh[7 - s], hl0);  hh0 = fmaf(HIc[s], wh[7 - s], hh0);
            ll1 = fmaf(LO[s],  wl[9 - s], ll1);  lh1 = fmaf(HIc[s], wl[9 - s], lh1);
            hl1 = fmaf(LO[s],  wh[9 - s], hl1);  hh1 = fmaf(HIc[s], wh[9 - s], hh1);
        }
        size_t b0 = blk * 529 + y * 23 + 2 * ph;
        out[b0]          = ll0;
        out[S2 + b0]     = lh0;
        out[2 * S2 + b0] = hl0;
        out[3 * S2 + b0] = hh0;
        if (2 * ph + 1 < 23) {
            out[b0 + 1]          = ll1;
            out[S2 + b0 + 1]     = lh1;
            out[2 * S2 + b0 + 1] = hl1;
            out[3 * S2 + b0 + 1] = hh1;
        }
    }
}

// ---------------------------------------------------------------------------
// Level-2 inverse, fused z+y, full, paired outputs (pair shares its 4 taps).
// ---------------------------------------------------------------------------
__global__ void i2_yz(const float* __restrict__ in, float* __restrict__ out,
                      long long S2) {
    __shared__ float si[4 * 529];
    __shared__ float sl[23 * 37];
    __shared__ float sh[23 * 37];
    const float LO[8] = FLO;
    const float HIc[8] = FHI;
    unsigned tid = threadIdx.x;
    size_t blk = blockIdx.x;
    for (int t = tid; t < 4 * 529; t += 256) {
        int slot = t / 529, r = t % 529;
        si[t] = in[(size_t)slot * S2 + blk * 529 + r];
    }
    __syncthreads();
    // z-IDWT, both dy rows, paired (i0=2m par0, i1=2m+1 par1 share js=m+1).
    for (int u = tid; u < 23 * 19; u += 256) {
        int m = u % 19, y = u / 19;
        int js = m + 1;
        float a0 = 0.f, a1 = 0.f, b0 = 0.f, b1 = 0.f;
#pragma unroll
        for (int d = 0; d < 4; d++) {
            int q = y * 23 + js + d;
            float v0 = si[q],           v1 = si[529 + q];
            float v2 = si[2 * 529 + q], v3 = si[3 * 529 + q];
            a0 = fmaf(v0, LO[2 * d + 1], a0);  a0 = fmaf(v1, HIc[2 * d + 1], a0);
            a1 = fmaf(v0, LO[2 * d],     a1);  a1 = fmaf(v1, HIc[2 * d],     a1);
            b0 = fmaf(v2, LO[2 * d + 1], b0);  b0 = fmaf(v3, HIc[2 * d + 1], b0);
            b1 = fmaf(v2, LO[2 * d],     b1);  b1 = fmaf(v3, HIc[2 * d],     b1);
        }
        sl[y * 37 + 2 * m] = a0;  sh[y * 37 + 2 * m] = b0;
        if (2 * m + 1 < 37) {
            sl[y * 37 + 2 * m + 1] = a1;  sh[y * 37 + 2 * m + 1] = b1;
        }
    }
    __syncthreads();
    float* op = out + blk * 1369;
    // y-IDWT, paired.
    for (int u = tid; u < 19 * 37; u += 256) {
        int z = u % 37, m = u / 37;
        int js = m + 1;
        float a0 = 0.f, a1 = 0.f;
#pragma unroll
        for (int d = 0; d < 4; d++) {
            float vl = sl[(js + d) * 37 + z];
            float vh = sh[(js + d) * 37 + z];
            a0 = fmaf(vl, LO[2 * d + 1], a0);  a0 = fmaf(vh, HIc[2 * d + 1], a0);
            a1 = fmaf(vl, LO[2 * d],     a1);  a1 = fmaf(vh, HIc[2 * d],     a1);
        }
        op[(2 * m) * 37 + z] = a0;
        if (2 * m + 1 < 37) op[(2 * m + 1) * 37 + z] = a1;
    }
}

// ---------------------------------------------------------------------------
// Level-1 inverse, fused z+y, lo-only, paired outputs. s1 row padded to 65.
// ---------------------------------------------------------------------------
__global__ void i1_yz(const float* __restrict__ in, float* __restrict__ out) {
    __shared__ float s0[37 * 37];
    __shared__ float s1[37 * 65];
    const float LO[8] = FLO;
    unsigned tid = threadIdx.x;
    size_t blk = blockIdx.x;
    const float* gp = in + blk * 1369;
#pragma unroll 3
    for (int t = tid; t < 1369; t += 256) s0[t] = gp[t];
    __syncthreads();
    // z-IDWT, paired: 37 y x 32 pairs.
    for (int u = tid; u < 37 * 32; u += 256) {
        int m = u & 31, y = u >> 5;
        int js = m + 1;
        float a0 = 0.f, a1 = 0.f;
#pragma unroll
        for (int d = 0; d < 4; d++) {
            float v = s0[y * 37 + js + d];
            a0 = fmaf(v, LO[2 * d + 1], a0);
            a1 = fmaf(v, LO[2 * d],     a1);
        }
        s1[y * 65 + 2 * m]     = a0;
        s1[y * 65 + 2 * m + 1] = a1;
    }
    __syncthreads();
    float* op = out + blk * 4096;
    // y-IDWT, paired: 32 pairs x 64 z.
    for (int u = tid; u < 32 * 64; u += 256) {
        int z = u & 63, m = u >> 6;
        int js = m + 1;
        float a0 = 0.f, a1 = 0.f;
#pragma unroll
        for (int d = 0; d < 4; d++) {
            float v = s1[(js + d) * 65 + z];
            a0 = fmaf(v, LO[2 * d + 1], a0);
            a1 = fmaf(v, LO[2 * d],     a1);
        }
        op[(2 * m) * 64 + z]     = a0;
        op[(2 * m + 1) * 64 + z] = a1;
    }
}

// ---------------------------------------------------------------------------
// Channel mix, ALL 8 bands in one launch (blockIdx.y = band).
// out[b,o,v] = sum_i in[b,i,v] * w_band[i,o,v]. i-loop unrolled x2 for MLP.
// ---------------------------------------------------------------------------
__global__ void chanmix_all(const float* __restrict__ in,
                            float* __restrict__ out, long long SBl,
                            const float* __restrict__ w0, const float* __restrict__ w1,
                            const float* __restrict__ w2, const float* __restrict__ w3,
                            const float* __restrict__ w4, const float* __restrict__ w5,
                            const float* __restrict__ w6, const float* __restrict__ w7) {
    __shared__ float s_in[320][32];
    int k = blockIdx.y;
    const float* w;
    switch (k) {
        case 0: w = w0; break; case 1: w = w1; break;
        case 2: w = w2; break; case 3: w = w3; break;
        case 4: w = w4; break; case 5: w = w5; break;
        case 6: w = w6; break; default: w = w7; break;
    }
    const float* bin = in  + (long long)k * SBl;
    float*       bout = out + (long long)k * SBl;

    int lane = threadIdx.x;
    int ty   = threadIdx.y;
    int v    = blockIdx.x * 32 + lane;
    bool valid = v < NV;
    int vc = valid ? v : (NV - 1);

    for (int r = ty; r < 320; r += 8)
        s_in[r][lane] = bin[(long long)r * NV + vc];
    __syncthreads();

    float acc[5][8];
#pragma unroll
    for (int a = 0; a < 5; a++)
#pragma unroll
        for (int b = 0; b < 8; b++) acc[a][b] = 0.f;

#pragma unroll 2
    for (int i = 0; i < 40; i += 2) {
        float xv0[8], xv1[8];
#pragma unroll
        for (int b = 0; b < 8; b++) {
            xv0[b] = s_in[b * 40 + i][lane];
            xv1[b] = s_in[b * 40 + i + 1][lane];
        }
        float wv0[5], wv1[5];
#pragma unroll
        for (int oo = 0; oo < 5; oo++) {
            int o = ty + oo * 8;
            wv0[oo] = w[((long long)i * 40 + o) * NV + vc];
            wv1[oo] = w[((long long)(i + 1) * 40 + o) * NV + vc];
        }
#pragma unroll
        for (int oo = 0; oo < 5; oo++)
#pragma unroll
            for (int b = 0; b < 8; b++) {
                acc[oo][b] = fmaf(xv0[b], wv0[oo], acc[oo][b]);
                acc[oo][b] = fmaf(xv1[b], wv1[oo], acc[oo][b]);
            }
    }
    if (!valid) return;
#pragma unroll
    for (int oo = 0; oo < 5; oo++) {
        int o = ty + oo * 8;
#pragma unroll
        for (int b = 0; b < 8; b++)
            bout[((long long)b * 40 + o) * NV + v] = acc[oo][b];
    }
}

// ---------------------------------------------------------------------------
extern "C" void kernel_launch(void* const* d_in, const int* in_sizes, int n_in,
                              void* d_out, int out_size) {
    const float* x = (const float*)d_in[0];
    float* out = (float*)d_out;

    float *b1, *b2;
    cudaGetSymbolAddress((void**)&b1, g_buf1);
    cudaGetSymbolAddress((void**)&b2, g_buf2);

    const long long S2  = 6263360LL;   // 320*37*23*23 (per yz-band volume)
    const long long SBl = 3893440LL;   // 320*23*23*23 (per final band volume)

    auto g = [](unsigned t) { return (t + 255u) / 256u; };

    // --- Level-1 forward: fused yz (lo), then x (lo) ------------------------
    f1_yz<<<320 * 64, 256>>>(x, b1);                        // -> (320,64,37,37)
    { unsigned T = 320u * 1369u;                            // -> (320,37,37,37)
      dwt_s<64, 1369, false><<<g(T), 256>>>(b1, b2, nullptr, T); }

    // --- Level-2 forward: fused yz (4 bands), then x (lo+hi over all 4) -----
    f2_yz<<<320 * 37, 256>>>(b2, b1, S2);                   // -> 4x(320,37,23,23)
    { unsigned T = 1280u * 529u;                            // -> 8x(320,23,23,23)
      dwt_s<37, 529, true><<<g(T), 256>>>(b1, b2, b2 + 4 * SBl, T); }

    // --- Channel mix: all 8 bands in one launch (slot == weight index k) ----
    chanmix_all<<<dim3((NV + 31) / 32, 8), dim3(32, 8)>>>(
        b2, b1, SBl,
        (const float*)d_in[1], (const float*)d_in[2],
        (const float*)d_in[3], (const float*)d_in[4],
        (const float*)d_in[5], (const float*)d_in[6],
        (const float*)d_in[7], (const float*)d_in[8]);

    // --- Level-2 inverse: x (lo+hi over all 4), then fused zy ---------------
    { unsigned T = 1280u * 529u;                            // -> 4x(320,37,23,23)
      idwt_s<23, 37, 529, true><<<g(T), 256>>>(b1, b1 + 4 * SBl, b2, T); }
    i2_yz<<<320 * 37, 256>>>(b2, b1, S2);                   // -> (320,37,37,37)

    // --- Level-1 inverse: x (lo), then fused zy (lo) -------------------------
    { unsigned T = 320u * 1369u;                            // -> (320,64,37,37)
      idwt_s<37, 64, 1369, false><<<g(T), 256>>>(b1, nullptr, b2, T); }
    i1_yz<<<320 * 64, 256>>>(b2, out);                      // -> (320,64,64,64)
}